// round 15
// baseline (speedup 1.0000x reference)
#include <cuda_runtime.h>
#include <cstdint>

// Shapes fixed by the problem: B=8, S=12, H=W=512
#define BS_TOTAL 96
#define HW 262144               // 512*512
#define CHUNKS 2
#define CHUNK (HW / CHUNKS)     // 131072 floats per block per array
#define THREADS 256
#define STAGE_ELEMS 2048        // 2 float4 per thread per array per stage
#define NSTAGES (CHUNK / STAGE_ELEMS)   // 64
#define NBUF 3                  // triple buffer, 96 KB dynamic SMEM
#define STAGE_BYTES (STAGE_ELEMS * 4)   // 8192 B per array
#define TX_BYTES (4 * STAGE_BYTES)      // 32768 B per stage
#define NPART 5                 // bce, inter, psum, tsum, att  (fp == psum)
#define GRID (CHUNKS * BS_TOTAL) // 192 — single wave

#define BUF_BYTES (NBUF * 4 * STAGE_BYTES)   // 98304
#define SMEM_DYN  BUF_BYTES

// Deterministic per-(bs,chunk) partials. Fully rewritten every launch.
__device__ float g_part[BS_TOTAL * CHUNKS * NPART];
// Last-block-done counter; last block resets it for graph replay.
__device__ unsigned int g_count = 0;

__inline__ __device__ float warp_sum(float v) {
    #pragma unroll
    for (int o = 16; o > 0; o >>= 1)
        v += __shfl_down_sync(0xffffffffu, v, o);
    return v;
}

__device__ __forceinline__ uint32_t smem_u32(const void* p) {
    return (uint32_t)__cvta_generic_to_shared(p);
}
__device__ __forceinline__ void mbar_init(uint32_t a, uint32_t cnt) {
    asm volatile("mbarrier.init.shared.b64 [%0], %1;" :: "r"(a), "r"(cnt) : "memory");
}
__device__ __forceinline__ void mbar_expect_tx(uint32_t a, uint32_t bytes) {
    asm volatile("mbarrier.arrive.expect_tx.shared.b64 _, [%0], %1;"
                 :: "r"(a), "r"(bytes) : "memory");
}
__device__ __forceinline__ void bulk_g2s(uint32_t dst, const float* src,
                                         uint32_t bytes, uint32_t mbar) {
    asm volatile("cp.async.bulk.shared::cta.global.mbarrier::complete_tx::bytes "
                 "[%0], [%1], %2, [%3];"
                 :: "r"(dst), "l"(src), "r"(bytes), "r"(mbar) : "memory");
}
__device__ __forceinline__ void mbar_wait(uint32_t a, uint32_t parity) {
    asm volatile(
        "{\n\t.reg .pred P;\n\t"
        "WAIT_%=:\n\t"
        "mbarrier.try_wait.parity.acquire.cta.shared::cta.b64 P, [%0], %1, 0x989680;\n\t"
        "@P bra.uni DONE_%=;\n\t"
        "bra.uni WAIT_%=;\n\t"
        "DONE_%=:\n\t}"
        :: "r"(a), "r"(parity) : "memory");
}
__device__ __forceinline__ void fence_proxy_async_s() {
    asm volatile("fence.proxy.async.shared::cta;" ::: "memory");
}

extern __shared__ __align__(128) unsigned char smem_dyn[];

__global__ void __launch_bounds__(THREADS)
loss_fused_kernel(const float* __restrict__ logits,
                  const float* __restrict__ probs,
                  const float* __restrict__ attmap,
                  const float* __restrict__ tgt,
                  const float* __restrict__ pprob,
                  const float* __restrict__ ptgt,
                  float* __restrict__ out) {
    __shared__ uint64_t mbar_s[NBUF];

    const int chunk = blockIdx.x;   // 0..CHUNKS-1
    const int bs    = blockIdx.y;   // 0..BS_TOTAL-1
    const size_t base = (size_t)bs * HW + (size_t)chunk * CHUNK;

    const float* src0 = logits + base;
    const float* src1 = probs  + base;
    const float* src2 = attmap + base;
    const float* src3 = tgt    + base;

    const uint32_t mb_base  = smem_u32(&mbar_s[0]);
    const uint32_t buf_base = smem_u32(smem_dyn);

    if (threadIdx.x == 0) {
        #pragma unroll
        for (int b = 0; b < NBUF; ++b) mbar_init(mb_base + 8 * b, 1);
        fence_proxy_async_s();   // make init visible to the async (TMA) proxy
    }
    __syncthreads();             // no thread may wait before init

    if (threadIdx.x == 0) {
        // prologue: stages 0..NBUF-1 in flight (96 KB per CTA)
        #pragma unroll
        for (int s = 0; s < NBUF; ++s) {
            const uint32_t mb = mb_base + 8 * s;
            mbar_expect_tx(mb, TX_BYTES);
            const uint32_t d = buf_base + s * (4 * STAGE_BYTES);
            const int off = s * STAGE_ELEMS;
            bulk_g2s(d,                   src0 + off, STAGE_BYTES, mb);
            bulk_g2s(d +     STAGE_BYTES, src1 + off, STAGE_BYTES, mb);
            bulk_g2s(d + 2 * STAGE_BYTES, src2 + off, STAGE_BYTES, mb);
            bulk_g2s(d + 3 * STAGE_BYTES, src3 + off, STAGE_BYTES, mb);
        }
    }

    float bce = 0.f, inter = 0.f, psum = 0.f, tsum = 0.f, attb = 0.f;

    #pragma unroll 3
    for (int s = 0; s < NSTAGES; ++s) {
        const int b = s % NBUF;
        const uint32_t mb = mb_base + 8 * b;
        mbar_wait(mb, (uint32_t)((s / NBUF) & 1));   // phase flips each reuse

        const float4* fb = reinterpret_cast<const float4*>(
            smem_dyn + (size_t)b * (4 * STAGE_BYTES));
        const int nf4 = STAGE_ELEMS / 4;   // 512 float4 per array

        // two float4 per array per thread
        #pragma unroll
        for (int r = 0; r < 2; ++r) {
            const int idx = threadIdx.x + r * THREADS;
            const float4 x4 = fb[0 * nf4 + idx];
            const float4 p4 = fb[1 * nf4 + idx];
            const float4 a4 = fb[2 * nf4 + idx];
            const float4 t4 = fb[3 * nf4 + idx];

            const float xs[4] = {x4.x, x4.y, x4.z, x4.w};
            const float ps[4] = {p4.x, p4.y, p4.z, p4.w};
            const float as[4] = {a4.x, a4.y, a4.z, a4.w};
            const float ts[4] = {t4.x, t4.y, t4.z, t4.w};

            // Log-batching: sum_j log(v_j) = log(prod_j v_j).
            //  - bce factors (1+e_j) in (1,16]: product exact-range.
            //  - att args in [1e-6, 1]: product of 4 >= 1e-24 > FLT_MIN.
            float prod_bce = 1.f;
            float prod_att = 1.f;

            #pragma unroll
            for (int j = 0; j < 4; ++j) {
                const float x = xs[j], p = ps[j], a = as[j], t = ts[j];

                // BCE-with-logits linear part: max(x,0) - x*t
                const float e = __expf(-fabsf(x));
                bce += fmaxf(x, 0.f) - x * t;
                prod_bce *= (1.f + e);

                // dice terms (psum doubles as fp-suppression sum: p > 0)
                inter = fmaf(p, t, inter);
                psum += p;
                tsum += t;

                // attention BCE vs hard target (t>0.5); a clipped >=1e-6,
                // so the reference's -100 log clamp is dead code.
                prod_att *= (t > 0.5f) ? a : (1.f - a);
            }

            bce  += __logf(prod_bce);
            attb -= __logf(prod_att);
        }

        __syncthreads();   // all reads of buffer b done before refill
        if (threadIdx.x == 0 && s + NBUF < NSTAGES) {
            const int off = (s + NBUF) * STAGE_ELEMS;
            mbar_expect_tx(mb, TX_BYTES);
            const uint32_t d = buf_base + b * (4 * STAGE_BYTES);
            bulk_g2s(d,                   src0 + off, STAGE_BYTES, mb);
            bulk_g2s(d +     STAGE_BYTES, src1 + off, STAGE_BYTES, mb);
            bulk_g2s(d + 2 * STAGE_BYTES, src2 + off, STAGE_BYTES, mb);
            bulk_g2s(d + 3 * STAGE_BYTES, src3 + off, STAGE_BYTES, mb);
        }
    }

    // ---- block reduce 5 values ----
    float v[NPART] = {bce, inter, psum, tsum, attb};
    __shared__ float smem_red[THREADS / 32][NPART];
    const int lane = threadIdx.x & 31;
    const int w    = threadIdx.x >> 5;

    #pragma unroll
    for (int k = 0; k < NPART; ++k) v[k] = warp_sum(v[k]);
    if (lane == 0) {
        #pragma unroll
        for (int k = 0; k < NPART; ++k) smem_red[w][k] = v[k];
    }
    __syncthreads();

    __shared__ bool s_last;
    if (w == 0) {
        #pragma unroll
        for (int k = 0; k < NPART; ++k)
            v[k] = (lane < THREADS / 32) ? smem_red[lane][k] : 0.f;
        #pragma unroll
        for (int k = 0; k < NPART; ++k) {
            #pragma unroll
            for (int o = 4; o > 0; o >>= 1)
                v[k] += __shfl_down_sync(0xffffffffu, v[k], o);
        }
        if (lane == 0) {
            float* dst = &g_part[(bs * CHUNKS + chunk) * NPART];
            #pragma unroll
            for (int k = 0; k < NPART; ++k) dst[k] = v[k];
            __threadfence();                          // publish partials
            const unsigned int done = atomicAdd(&g_count, 1u);
            s_last = (done == GRID - 1);
        }
    }
    __syncthreads();
    if (!s_last) return;

    // ======== last block only: finalize (partials are L2-hot) ========
    __threadfence();  // acquire side of the handshake

    __shared__ float sh[BS_TOTAL][8];
    const int mybs = threadIdx.x;
    if (mybs < BS_TOTAL) {
        float s[NPART] = {0.f, 0.f, 0.f, 0.f, 0.f};
        #pragma unroll
        for (int c = 0; c < CHUNKS; ++c) {
            const float* src = &g_part[(mybs * CHUNKS + c) * NPART];
            #pragma unroll
            for (int k = 0; k < NPART; ++k) s[k] += src[k];
        }
        const float invHW = 1.f / (float)HW;
        const float seg_bce = s[0] * invHW;
        const float dice    = 1.f - (2.f * s[1] + 1e-6f) / (s[2] + s[3] + 1e-6f);
        const float fp_bs   = s[2] * invHW;          // mean(max(p,0)) == mean(p)
        const float att_bs  = s[4] * invHW;

        const float t = ptgt[mybs];
        const float p = pprob[mybs];
        const float m = (t != 0.f) ? 1.f : 0.f;

        // presence BCE (p clipped to [1e-6, 1-1e-6]: -100 clamps dead)
        const float pbce = -(t * logf(p) + (1.f - t) * log1pf(-p));

        // confidence calibration penalty
        float conf = 0.f;
        if (t == 0.f && p > 0.5f) { const float d = p - 0.5f; conf = d * d; }
        if (t == 1.f && p < 0.5f) { const float d = 0.5f - p; conf = d * d; }

        sh[mybs][0] = seg_bce * m;
        sh[mybs][1] = dice * m;
        sh[mybs][2] = fp_bs * (1.f - m);
        sh[mybs][3] = att_bs * m;
        sh[mybs][4] = pbce;
        sh[mybs][5] = conf;
        sh[mybs][6] = m;          // n_valid
        sh[mybs][7] = 1.f - m;    // n_absent
    }
    __syncthreads();

    if (threadIdx.x == 0) {
        float acc[8] = {0.f, 0.f, 0.f, 0.f, 0.f, 0.f, 0.f, 0.f};
        for (int i2 = 0; i2 < BS_TOTAL; ++i2)
            #pragma unroll
            for (int k = 0; k < 8; ++k) acc[k] += sh[i2][k];

        const float n_valid  = acc[6];
        const float n_absent = acc[7];

        const float seg_loss  = (n_valid  > 0.f) ? acc[0] / fmaxf(n_valid, 1.f)  : 0.f;
        const float dice_loss = (n_valid  > 0.f) ? acc[1] / fmaxf(n_valid, 1.f)  : 0.f;
        const float fp_loss   = (n_absent > 0.f) ? acc[2] / fmaxf(n_absent, 1.f) : 0.f;
        const float inv_bs    = 1.f / (float)BS_TOTAL;
        const float att_loss  = acc[3] * inv_bs;
        const float abs_loss  = acc[4] * inv_bs;
        const float conf_loss = acc[5] * inv_bs;

        const float total = 1.0f * seg_loss + 1.0f * dice_loss
                          + 2.0f * abs_loss + 0.3f * att_loss
                          + 0.1f * conf_loss + 0.5f * fp_loss;

        out[0] = total;
        out[1] = seg_loss;
        out[2] = dice_loss;
        out[3] = abs_loss;
        out[4] = att_loss;
        out[5] = conf_loss;
        out[6] = fp_loss;

        g_count = 0;   // reset for next graph replay
    }
}

extern "C" void kernel_launch(void* const* d_in, const int* in_sizes, int n_in,
                              void* d_out, int out_size) {
    // metadata order = reference signature order:
    // 0: seg_logits [8,12,512,512]
    // 1: seg_probs  [8,12,512,512]
    // 2: presence_probs [8,12]
    // 3: attention_maps [8,12,512,512]
    // 4: seg_targets [8,12,512,512]
    // 5: presence_targets [8,12]
    const float* seg_logits = (const float*)d_in[0];
    const float* seg_probs  = (const float*)d_in[1];
    const float* pres_probs = (const float*)d_in[2];
    const float* att_maps   = (const float*)d_in[3];
    const float* seg_tgts   = (const float*)d_in[4];
    const float* pres_tgts  = (const float*)d_in[5];
    float* out = (float*)d_out;

    // idempotent; >48KB dynamic smem requires opt-in
    cudaFuncSetAttribute(loss_fused_kernel,
                         cudaFuncAttributeMaxDynamicSharedMemorySize, SMEM_DYN);

    dim3 grid(CHUNKS, BS_TOTAL);
    loss_fused_kernel<<<grid, THREADS, SMEM_DYN>>>(seg_logits, seg_probs, att_maps,
                                                   seg_tgts, pres_probs, pres_tgts, out);
}

// round 16
// speedup vs baseline: 1.0355x; 1.0355x over previous
#include <cuda_runtime.h>
#include <cstdint>

// Shapes fixed by the problem: B=8, S=12, H=W=512
#define BS_TOTAL 96
#define HW 262144               // 512*512
#define CHUNKS 4
#define CHUNK (HW / CHUNKS)     // 65536 floats per block per array
#define THREADS 256
#define STAGE_ELEMS 2048        // 2 float4 per thread per array per stage
#define NSTAGES (CHUNK / STAGE_ELEMS)   // 32
#define NBUF 2                  // double buffer, 64 KB dynamic SMEM
#define STAGE_BYTES (STAGE_ELEMS * 4)   // 8192 B per array
#define TX_BYTES (4 * STAGE_BYTES)      // 32768 B per stage
#define NPART 5                 // bce, inter, psum, tsum, att  (fp == psum)
#define GRID (CHUNKS * BS_TOTAL) // 384 — single wave at 3 CTAs/SM

#define BUF_BYTES (NBUF * 4 * STAGE_BYTES)   // 65536
#define SMEM_DYN  BUF_BYTES

// Deterministic per-(bs,chunk) partials. Fully rewritten every launch.
__device__ float g_part[BS_TOTAL * CHUNKS * NPART];
// Last-block-done counter; last block resets it for graph replay.
__device__ unsigned int g_count = 0;

__inline__ __device__ float warp_sum(float v) {
    #pragma unroll
    for (int o = 16; o > 0; o >>= 1)
        v += __shfl_down_sync(0xffffffffu, v, o);
    return v;
}

__device__ __forceinline__ uint32_t smem_u32(const void* p) {
    return (uint32_t)__cvta_generic_to_shared(p);
}
__device__ __forceinline__ void mbar_init(uint32_t a, uint32_t cnt) {
    asm volatile("mbarrier.init.shared.b64 [%0], %1;" :: "r"(a), "r"(cnt) : "memory");
}
__device__ __forceinline__ void mbar_expect_tx(uint32_t a, uint32_t bytes) {
    asm volatile("mbarrier.arrive.expect_tx.shared.b64 _, [%0], %1;"
                 :: "r"(a), "r"(bytes) : "memory");
}
__device__ __forceinline__ void bulk_g2s(uint32_t dst, const float* src,
                                         uint32_t bytes, uint32_t mbar) {
    asm volatile("cp.async.bulk.shared::cta.global.mbarrier::complete_tx::bytes "
                 "[%0], [%1], %2, [%3];"
                 :: "r"(dst), "l"(src), "r"(bytes), "r"(mbar) : "memory");
}
__device__ __forceinline__ void mbar_wait(uint32_t a, uint32_t parity) {
    asm volatile(
        "{\n\t.reg .pred P;\n\t"
        "WAIT_%=:\n\t"
        "mbarrier.try_wait.parity.acquire.cta.shared::cta.b64 P, [%0], %1, 0x989680;\n\t"
        "@P bra.uni DONE_%=;\n\t"
        "bra.uni WAIT_%=;\n\t"
        "DONE_%=:\n\t}"
        :: "r"(a), "r"(parity) : "memory");
}
__device__ __forceinline__ void fence_proxy_async_s() {
    asm volatile("fence.proxy.async.shared::cta;" ::: "memory");
}

extern __shared__ __align__(128) unsigned char smem_dyn[];

__global__ void __launch_bounds__(THREADS)
loss_fused_kernel(const float* __restrict__ logits,
                  const float* __restrict__ probs,
                  const float* __restrict__ attmap,
                  const float* __restrict__ tgt,
                  const float* __restrict__ pprob,
                  const float* __restrict__ ptgt,
                  float* __restrict__ out) {
    __shared__ uint64_t mbar_s[NBUF];

    const int chunk = blockIdx.x;   // 0..CHUNKS-1
    const int bs    = blockIdx.y;   // 0..BS_TOTAL-1
    const size_t base = (size_t)bs * HW + (size_t)chunk * CHUNK;

    const float* src0 = logits + base;
    const float* src1 = probs  + base;
    const float* src2 = attmap + base;
    const float* src3 = tgt    + base;

    const uint32_t mb0 = smem_u32(&mbar_s[0]);
    const uint32_t mb1 = smem_u32(&mbar_s[1]);
    const uint32_t buf_base = smem_u32(smem_dyn);

    if (threadIdx.x == 0) {
        mbar_init(mb0, 1);
        mbar_init(mb1, 1);
        fence_proxy_async_s();   // make init visible to the async (TMA) proxy
    }
    __syncthreads();             // no thread may wait before init

    if (threadIdx.x == 0) {
        // prologue: stages 0 and 1 in flight (64 KB per CTA)
        #pragma unroll
        for (int s = 0; s < 2; ++s) {
            const uint32_t mb = s ? mb1 : mb0;
            mbar_expect_tx(mb, TX_BYTES);
            const uint32_t d = buf_base + s * (4 * STAGE_BYTES);
            const int off = s * STAGE_ELEMS;
            bulk_g2s(d,                   src0 + off, STAGE_BYTES, mb);
            bulk_g2s(d +     STAGE_BYTES, src1 + off, STAGE_BYTES, mb);
            bulk_g2s(d + 2 * STAGE_BYTES, src2 + off, STAGE_BYTES, mb);
            bulk_g2s(d + 3 * STAGE_BYTES, src3 + off, STAGE_BYTES, mb);
        }
    }

    float bce = 0.f, inter = 0.f, psum = 0.f, tsum = 0.f, attb = 0.f;

    #pragma unroll 2
    for (int s = 0; s < NSTAGES; ++s) {
        const int b = s & 1;
        const uint32_t mb = b ? mb1 : mb0;
        mbar_wait(mb, (s >> 1) & 1);   // buffer b phase: 0,1,0,1,...

        const float4* fb = reinterpret_cast<const float4*>(
            smem_dyn + (size_t)b * (4 * STAGE_BYTES));
        const int nf4 = STAGE_ELEMS / 4;   // 512 float4 per array

        // two float4 per array per thread
        #pragma unroll
        for (int r = 0; r < 2; ++r) {
            const int idx = threadIdx.x + r * THREADS;
            const float4 x4 = fb[0 * nf4 + idx];
            const float4 p4 = fb[1 * nf4 + idx];
            const float4 a4 = fb[2 * nf4 + idx];
            const float4 t4 = fb[3 * nf4 + idx];

            const float xs[4] = {x4.x, x4.y, x4.z, x4.w};
            const float ps[4] = {p4.x, p4.y, p4.z, p4.w};
            const float as[4] = {a4.x, a4.y, a4.z, a4.w};
            const float ts[4] = {t4.x, t4.y, t4.z, t4.w};

            #pragma unroll
            for (int j = 0; j < 4; ++j) {
                const float x = xs[j], p = ps[j], a = as[j], t = ts[j];

                // BCE with logits: max(x,0) - x*t + log1p(exp(-|x|))
                const float e = __expf(-fabsf(x));
                bce += fmaxf(x, 0.f) - x * t + __logf(1.f + e);

                // dice terms (psum doubles as fp-suppression sum: p > 0)
                inter = fmaf(p, t, inter);
                psum += p;
                tsum += t;

                // attention BCE vs hard target (t>0.5); a clipped >=1e-6,
                // so the reference's -100 log clamp is dead code.
                const float arg = (t > 0.5f) ? a : (1.f - a);
                attb -= __logf(arg);
            }
        }

        __syncthreads();   // all reads of buffer b done before refill
        if (threadIdx.x == 0 && s + 2 < NSTAGES) {
            const int off = (s + 2) * STAGE_ELEMS;
            mbar_expect_tx(mb, TX_BYTES);
            const uint32_t d = buf_base + b * (4 * STAGE_BYTES);
            bulk_g2s(d,                   src0 + off, STAGE_BYTES, mb);
            bulk_g2s(d +     STAGE_BYTES, src1 + off, STAGE_BYTES, mb);
            bulk_g2s(d + 2 * STAGE_BYTES, src2 + off, STAGE_BYTES, mb);
            bulk_g2s(d + 3 * STAGE_BYTES, src3 + off, STAGE_BYTES, mb);
        }
    }

    // ---- block reduce 5 values ----
    float v[NPART] = {bce, inter, psum, tsum, attb};
    __shared__ float smem_red[THREADS / 32][NPART];
    const int lane = threadIdx.x & 31;
    const int w    = threadIdx.x >> 5;

    #pragma unroll
    for (int k = 0; k < NPART; ++k) v[k] = warp_sum(v[k]);
    if (lane == 0) {
        #pragma unroll
        for (int k = 0; k < NPART; ++k) smem_red[w][k] = v[k];
    }
    __syncthreads();

    __shared__ bool s_last;
    if (w == 0) {
        #pragma unroll
        for (int k = 0; k < NPART; ++k)
            v[k] = (lane < THREADS / 32) ? smem_red[lane][k] : 0.f;
        #pragma unroll
        for (int k = 0; k < NPART; ++k) {
            #pragma unroll
            for (int o = 4; o > 0; o >>= 1)
                v[k] += __shfl_down_sync(0xffffffffu, v[k], o);
        }
        if (lane == 0) {
            float* dst = &g_part[(bs * CHUNKS + chunk) * NPART];
            #pragma unroll
            for (int k = 0; k < NPART; ++k) dst[k] = v[k];
            __threadfence();                          // publish partials
            const unsigned int done = atomicAdd(&g_count, 1u);
            s_last = (done == GRID - 1);
        }
    }
    __syncthreads();
    if (!s_last) return;

    // ======== last block only: finalize (partials are L2-hot) ========
    __threadfence();  // acquire side of the handshake

    __shared__ float sh[BS_TOTAL][8];
    const int mybs = threadIdx.x;
    if (mybs < BS_TOTAL) {
        float s[NPART] = {0.f, 0.f, 0.f, 0.f, 0.f};
        #pragma unroll
        for (int c = 0; c < CHUNKS; ++c) {
            const float* src = &g_part[(mybs * CHUNKS + c) * NPART];
            #pragma unroll
            for (int k = 0; k < NPART; ++k) s[k] += src[k];
        }
        const float invHW = 1.f / (float)HW;
        const float seg_bce = s[0] * invHW;
        const float dice    = 1.f - (2.f * s[1] + 1e-6f) / (s[2] + s[3] + 1e-6f);
        const float fp_bs   = s[2] * invHW;          // mean(max(p,0)) == mean(p)
        const float att_bs  = s[4] * invHW;

        const float t = ptgt[mybs];
        const float p = pprob[mybs];
        const float m = (t != 0.f) ? 1.f : 0.f;

        // presence BCE (p clipped to [1e-6, 1-1e-6]: -100 clamps dead)
        const float pbce = -(t * logf(p) + (1.f - t) * log1pf(-p));

        // confidence calibration penalty
        float conf = 0.f;
        if (t == 0.f && p > 0.5f) { const float d = p - 0.5f; conf = d * d; }
        if (t == 1.f && p < 0.5f) { const float d = 0.5f - p; conf = d * d; }

        sh[mybs][0] = seg_bce * m;
        sh[mybs][1] = dice * m;
        sh[mybs][2] = fp_bs * (1.f - m);
        sh[mybs][3] = att_bs * m;
        sh[mybs][4] = pbce;
        sh[mybs][5] = conf;
        sh[mybs][6] = m;          // n_valid
        sh[mybs][7] = 1.f - m;    // n_absent
    }
    __syncthreads();

    if (threadIdx.x == 0) {
        float acc[8] = {0.f, 0.f, 0.f, 0.f, 0.f, 0.f, 0.f, 0.f};
        for (int i2 = 0; i2 < BS_TOTAL; ++i2)
            #pragma unroll
            for (int k = 0; k < 8; ++k) acc[k] += sh[i2][k];

        const float n_valid  = acc[6];
        const float n_absent = acc[7];

        const float seg_loss  = (n_valid  > 0.f) ? acc[0] / fmaxf(n_valid, 1.f)  : 0.f;
        const float dice_loss = (n_valid  > 0.f) ? acc[1] / fmaxf(n_valid, 1.f)  : 0.f;
        const float fp_loss   = (n_absent > 0.f) ? acc[2] / fmaxf(n_absent, 1.f) : 0.f;
        const float inv_bs    = 1.f / (float)BS_TOTAL;
        const float att_loss  = acc[3] * inv_bs;
        const float abs_loss  = acc[4] * inv_bs;
        const float conf_loss = acc[5] * inv_bs;

        const float total = 1.0f * seg_loss + 1.0f * dice_loss
                          + 2.0f * abs_loss + 0.3f * att_loss
                          + 0.1f * conf_loss + 0.5f * fp_loss;

        out[0] = total;
        out[1] = seg_loss;
        out[2] = dice_loss;
        out[3] = abs_loss;
        out[4] = att_loss;
        out[5] = conf_loss;
        out[6] = fp_loss;

        g_count = 0;   // reset for next graph replay
    }
}

extern "C" void kernel_launch(void* const* d_in, const int* in_sizes, int n_in,
                              void* d_out, int out_size) {
    // metadata order = reference signature order:
    // 0: seg_logits [8,12,512,512]
    // 1: seg_probs  [8,12,512,512]
    // 2: presence_probs [8,12]
    // 3: attention_maps [8,12,512,512]
    // 4: seg_targets [8,12,512,512]
    // 5: presence_targets [8,12]
    const float* seg_logits = (const float*)d_in[0];
    const float* seg_probs  = (const float*)d_in[1];
    const float* pres_probs = (const float*)d_in[2];
    const float* att_maps   = (const float*)d_in[3];
    const float* seg_tgts   = (const float*)d_in[4];
    const float* pres_tgts  = (const float*)d_in[5];
    float* out = (float*)d_out;

    // idempotent; >48KB dynamic smem requires opt-in
    cudaFuncSetAttribute(loss_fused_kernel,
                         cudaFuncAttributeMaxDynamicSharedMemorySize, SMEM_DYN);

    dim3 grid(CHUNKS, BS_TOTAL);
    loss_fused_kernel<<<grid, THREADS, SMEM_DYN>>>(seg_logits, seg_probs, att_maps,
                                                   seg_tgts, pres_probs, pres_tgts, out);
}